// round 1
// baseline (speedup 1.0000x reference)
#include <cuda_runtime.h>
#include <cuda_bf16.h>
#include <math.h>
#include <stdint.h>

// ---------------- problem constants ----------------
#define B   2
#define S   2048
#define D   2048
#define HQ  16
#define HKV 8
#define HD  128
#define FF  8192
#define KCAP 256              // int(0.125 * 2048)
#define BSROWS (B*S)          // 4096
#define EPSF 1e-6f

// ---------------- device scratch (static, allowed) ----------------
__device__ float d_rw[BSROWS];
__device__ float d_thresh[B];
__device__ int   d_selidx[BSROWS];
__device__ int   d_selcnt[B];
__device__ int   d_off[B+1];
__device__ int   d_rows[1];
__device__ int   d_row_b[BSROWS];
__device__ int   d_row_p[BSROWS];
__device__ float d_x  [(size_t)BSROWS*D];
__device__ float d_h  [(size_t)BSROWS*D];
__device__ float d_q  [(size_t)BSROWS*HQ*HD];
__device__ float d_k  [(size_t)BSROWS*HKV*HD];
__device__ float d_v  [(size_t)BSROWS*HKV*HD];
__device__ float d_ctx[(size_t)BSROWS*HQ*HD];
__device__ float d_gg [(size_t)BSROWS*FF];
__device__ float d_uu [(size_t)BSROWS*FF];

// ---------------- router: rw[b,s] = hidden[b,s,:] . router_w ----------------
__global__ void router_kernel(const float* __restrict__ hs, const float* __restrict__ rwv) {
    int row  = blockIdx.x * 8 + (threadIdx.x >> 5);
    int lane = threadIdx.x & 31;
    if (row >= BSROWS) return;
    const float* x = hs + (size_t)row * D;
    float s = 0.f;
    for (int i = lane; i < D; i += 32) s += x[i] * rwv[i];
    #pragma unroll
    for (int o = 16; o; o >>= 1) s += __shfl_xor_sync(0xffffffffu, s, o);
    if (lane == 0) d_rw[row] = s;
}

// ---------------- per-batch top-k threshold via bitonic sort ----------------
__global__ void topk_kernel() {
    __shared__ float s[S];
    int b = blockIdx.x;
    int t = threadIdx.x;               // 1024 threads
    s[t]        = d_rw[b*S + t];
    s[t + 1024] = d_rw[b*S + t + 1024];
    for (int k = 2; k <= S; k <<= 1) {
        for (int j = k >> 1; j > 0; j >>= 1) {
            __syncthreads();
            for (int i = t; i < S; i += 1024) {
                int ixj = i ^ j;
                if (ixj > i) {
                    bool up = ((i & k) == 0);     // ascending segment
                    float a = s[i], c = s[ixj];
                    if ((a > c) == up) { s[i] = c; s[ixj] = a; }
                }
            }
        }
    }
    __syncthreads();
    if (t == 0) d_thresh[b] = s[S - KCAP];   // k-th largest
}

// ---------------- order-preserving compaction (one warp per batch) ----------------
__global__ void select_kernel() {
    int b = blockIdx.x;
    int lane = threadIdx.x;
    if (lane >= 32) return;
    float th = d_thresh[b];
    int total = 0;
    for (int c = 0; c < S/32; c++) {
        int idx = c*32 + lane;
        bool f = d_rw[b*S + idx] >= th;
        unsigned m = __ballot_sync(0xffffffffu, f);
        int pre = __popc(m & ((1u << lane) - 1u));
        if (f) d_selidx[b*S + total + pre] = idx;
        total += __popc(m);
    }
    if (lane == 0) d_selcnt[b] = total;
}

// ---------------- build global compacted row map ----------------
__global__ void map_kernel() {
    int t = threadIdx.x;
    int c0 = d_selcnt[0], c1 = d_selcnt[1];
    if (t == 0) { d_off[0]=0; d_off[1]=c0; d_off[2]=c0+c1; d_rows[0]=c0+c1; }
    for (int i = t; i < c0; i += blockDim.x) { d_row_b[i]      = 0; d_row_p[i]      = d_selidx[i]; }
    for (int i = t; i < c1; i += blockDim.x) { d_row_b[c0 + i] = 1; d_row_p[c0 + i] = d_selidx[S + i]; }
}

// ---------------- gather selected hidden rows into d_x ----------------
__global__ void gather_kernel(const float* __restrict__ hs) {
    int g = blockIdx.x;
    if (g >= d_rows[0]) return;
    int b = d_row_b[g], p = d_row_p[g];
    const float4* src = (const float4*)(hs + ((size_t)b*S + p) * D);
    float4* dst = (float4*)(d_x + (size_t)g * D);
    for (int i = threadIdx.x; i < D/4; i += 256) dst[i] = src[i];
}

// ---------------- rmsnorm over compacted rows ----------------
__global__ void rmsnorm_kernel(const float* __restrict__ in, float* __restrict__ out,
                               const float* __restrict__ w) {
    int g = blockIdx.x;
    if (g >= d_rows[0]) return;
    const float* row = in + (size_t)g * D;
    float ss = 0.f;
    for (int i = threadIdx.x; i < D; i += 256) { float v = row[i]; ss += v*v; }
    __shared__ float red[8];
    int lane = threadIdx.x & 31, wid = threadIdx.x >> 5;
    #pragma unroll
    for (int o = 16; o; o >>= 1) ss += __shfl_xor_sync(0xffffffffu, ss, o);
    if (lane == 0) red[wid] = ss;
    __syncthreads();
    if (threadIdx.x == 0) {
        float v = 0.f;
        #pragma unroll
        for (int i = 0; i < 8; i++) v += red[i];
        red[0] = v;
    }
    __syncthreads();
    float inv = rsqrtf(red[0] / (float)D + EPSF);
    for (int i = threadIdx.x; i < D; i += 256) out[(size_t)g*D + i] = row[i] * inv * w[i];
}

// ---------------- fp32 SGEMM (NT): C[M,N] = A[M,K] @ W[N,K]^T (+bias)(+R) ----------------
// BM=BN=64, BK=16, 256 threads, 4x4 per thread
__global__ void sgemm_nt(const float* __restrict__ A, const float* __restrict__ W,
                         const float* __restrict__ bias, const float* __restrict__ R,
                         float* __restrict__ C, int N, int K) {
    int rows = d_rows[0];
    int m0 = blockIdx.y * 64;
    if (m0 >= rows) return;
    int n0 = blockIdx.x * 64;

    __shared__ __align__(16) float As[16][64];
    __shared__ __align__(16) float Bs[16][64];

    int tid = threadIdx.x;
    int tx = tid & 15, ty = tid >> 4;
    int la_row = tid >> 2;
    int la_k   = (tid & 3) << 2;

    bool a_ok = (m0 + la_row) < rows;
    const float* Arow = A + (size_t)(m0 + la_row) * K;
    const float* Wrow = W + (size_t)(n0 + la_row) * K;

    float acc[4][4];
    #pragma unroll
    for (int i = 0; i < 4; i++)
        #pragma unroll
        for (int j = 0; j < 4; j++) acc[i][j] = 0.f;

    for (int k0 = 0; k0 < K; k0 += 16) {
        float4 av = a_ok ? *(const float4*)(Arow + k0 + la_k) : make_float4(0.f,0.f,0.f,0.f);
        float4 wv = *(const float4*)(Wrow + k0 + la_k);
        __syncthreads();
        As[la_k+0][la_row]=av.x; As[la_k+1][la_row]=av.y; As[la_k+2][la_row]=av.z; As[la_k+3][la_row]=av.w;
        Bs[la_k+0][la_row]=wv.x; Bs[la_k+1][la_row]=wv.y; Bs[la_k+2][la_row]=wv.z; Bs[la_k+3][la_row]=wv.w;
        __syncthreads();
        #pragma unroll
        for (int kk = 0; kk < 16; kk++) {
            float4 a = *(const float4*)(&As[kk][ty*4]);
            float4 bb = *(const float4*)(&Bs[kk][tx*4]);
            acc[0][0] += a.x*bb.x; acc[0][1] += a.x*bb.y; acc[0][2] += a.x*bb.z; acc[0][3] += a.x*bb.w;
            acc[1][0] += a.y*bb.x; acc[1][1] += a.y*bb.y; acc[1][2] += a.y*bb.z; acc[1][3] += a.y*bb.w;
            acc[2][0] += a.z*bb.x; acc[2][1] += a.z*bb.y; acc[2][2] += a.z*bb.z; acc[2][3] += a.z*bb.w;
            acc[3][0] += a.w*bb.x; acc[3][1] += a.w*bb.y; acc[3][2] += a.w*bb.z; acc[3][3] += a.w*bb.w;
        }
    }
    #pragma unroll
    for (int i = 0; i < 4; i++) {
        int m = m0 + ty*4 + i;
        if (m >= rows) continue;
        size_t base = (size_t)m * N + n0 + tx*4;
        #pragma unroll
        for (int j = 0; j < 4; j++) {
            float v = acc[i][j];
            if (bias) v += bias[n0 + tx*4 + j];
            if (R)    v += R[base + j];
            C[base + j] = v;
        }
    }
}

// ---------------- RoPE on compacted q/k at absolute position p ----------------
__global__ void rope_kernel() {
    int g = blockIdx.x;
    if (g >= d_rows[0]) return;
    float fp = (float)d_row_p[g];
    const float L2_10000 = 13.287712379549449f;
    for (int idx = threadIdx.x; idx < (HQ + HKV) * 64; idx += 256) {
        int head = idx >> 6;
        int i = idx & 63;
        float inv = exp2f(-(float)i * (L2_10000 / 64.0f));
        float fr = fp * inv;
        float c = cosf(fr), s = sinf(fr);
        float* ptr;
        if (head < HQ) ptr = d_q + (size_t)g*(HQ*HD) + head*HD;
        else           ptr = d_k + (size_t)g*(HKV*HD) + (head-HQ)*HD;
        float x1 = ptr[i], x2 = ptr[i+64];
        ptr[i]    = x1*c - x2*s;
        ptr[i+64] = x2*c + x1*s;
    }
}

// ---------------- attention: warp per (query-row, head), online softmax ----------------
// keys = selected keys with rank <= r, plus zc = p - r zero-score/zero-value keys
__global__ void attn_kernel() {
    int g = blockIdx.x;
    if (g >= d_rows[0]) return;
    int h = threadIdx.y + blockIdx.y * 8;
    int b = d_row_b[g];
    int off = d_off[b];
    int r = g - off;
    int p = d_row_p[g];
    int lane = threadIdx.x;
    int kvh = h >> 1;                      // repeat(k, 2) -> head h uses kv h/2

    float4 qv = *(const float4*)(d_q + (size_t)g*(HQ*HD) + h*HD + lane*4);
    const float scale = 0.08838834764831843f;  // 1/sqrt(128)

    float m = -INFINITY, l = 0.f;
    float4 acc = make_float4(0.f, 0.f, 0.f, 0.f);

    for (int j = 0; j <= r; j++) {
        const float* kp = d_k + (size_t)(off + j)*(HKV*HD) + kvh*HD;
        float4 kv = *(const float4*)(kp + lane*4);
        float sdot = qv.x*kv.x + qv.y*kv.y + qv.z*kv.z + qv.w*kv.w;
        #pragma unroll
        for (int o = 16; o; o >>= 1) sdot += __shfl_xor_sync(0xffffffffu, sdot, o);
        float sc = sdot * scale;
        float mn = fmaxf(m, sc);
        float eo = expf(m - mn);
        float ec = expf(sc - mn);
        const float* vp = d_v + (size_t)(off + j)*(HKV*HD) + kvh*HD;
        float4 vv = *(const float4*)(vp + lane*4);
        l = l*eo + ec;
        acc.x = acc.x*eo + ec*vv.x;
        acc.y = acc.y*eo + ec*vv.y;
        acc.z = acc.z*eo + ec*vv.z;
        acc.w = acc.w*eo + ec*vv.w;
        m = mn;
    }
    int zc = p - r;   // causal window positions with zero keys
    if (zc > 0) {
        float mn = fmaxf(m, 0.f);
        float eo = expf(m - mn);
        l = l*eo + (float)zc * expf(-mn);
        acc.x *= eo; acc.y *= eo; acc.z *= eo; acc.w *= eo;
        m = mn;
    }
    float invl = 1.f / l;
    float4 o4 = make_float4(acc.x*invl, acc.y*invl, acc.z*invl, acc.w*invl);
    *(float4*)(d_ctx + (size_t)g*(HQ*HD) + h*HD + lane*4) = o4;
}

// ---------------- silu(g)*u in place into d_gg ----------------
__global__ void silu_mul_kernel() {
    int g = blockIdx.x;
    if (g >= d_rows[0]) return;
    size_t base = (size_t)g * FF;
    for (int i = threadIdx.x; i < FF; i += 256) {
        float x = d_gg[base + i];
        float u = d_uu[base + i];
        d_gg[base + i] = (x / (1.f + expf(-x))) * u;
    }
}

// ---------------- output: copy-through then scatter selected rows ----------------
__global__ void copy_kernel(const float* __restrict__ hs, float* __restrict__ out) {
    size_t i = ((size_t)blockIdx.x * 256 + threadIdx.x);
    ((float4*)out)[i] = ((const float4*)hs)[i];
}

__global__ void scatter_kernel(float* __restrict__ out) {
    int g = blockIdx.x;
    if (g >= d_rows[0]) return;
    int b = d_row_b[g], p = d_row_p[g];
    float sc = d_rw[b*S + p];
    float* dst = out + ((size_t)b*S + p) * D;
    const float* src = d_x + (size_t)g * D;
    for (int i = threadIdx.x; i < D; i += 256) dst[i] = src[i] * sc;
}

// ---------------- launch ----------------
extern "C" void kernel_launch(void* const* d_in, const int* in_sizes, int n_in,
                              void* d_out, int out_size) {
    const float* hs    = (const float*)d_in[0];
    const float* rwv   = (const float*)d_in[1];
    const float* wq    = (const float*)d_in[2];
    const float* bq    = (const float*)d_in[3];
    const float* wk    = (const float*)d_in[4];
    const float* bk    = (const float*)d_in[5];
    const float* wv    = (const float*)d_in[6];
    const float* bv    = (const float*)d_in[7];
    const float* wo    = (const float*)d_in[8];
    const float* wgate = (const float*)d_in[9];
    const float* wup   = (const float*)d_in[10];
    const float* wdown = (const float*)d_in[11];
    const float* ln1w  = (const float*)d_in[12];
    const float* ln2w  = (const float*)d_in[13];
    float* out = (float*)d_out;

    float *px, *ph, *pq, *pk, *pv, *pctx, *pg, *pu;
    cudaGetSymbolAddress((void**)&px,   d_x);
    cudaGetSymbolAddress((void**)&ph,   d_h);
    cudaGetSymbolAddress((void**)&pq,   d_q);
    cudaGetSymbolAddress((void**)&pk,   d_k);
    cudaGetSymbolAddress((void**)&pv,   d_v);
    cudaGetSymbolAddress((void**)&pctx, d_ctx);
    cudaGetSymbolAddress((void**)&pg,   d_gg);
    cudaGetSymbolAddress((void**)&pu,   d_uu);

    // 1. router
    router_kernel<<<BSROWS/8, 256>>>(hs, rwv);
    // 2. threshold per batch
    topk_kernel<<<B, 1024>>>();
    // 3. compaction
    select_kernel<<<B, 32>>>();
    map_kernel<<<1, 1024>>>();
    // 4. gather + rmsnorm1
    gather_kernel<<<BSROWS, 256>>>(hs);
    rmsnorm_kernel<<<BSROWS, 256>>>(px, ph, ln1w);
    // 5. q/k/v projections
    sgemm_nt<<<dim3((HQ*HD)/64,  BSROWS/64), 256>>>(ph, wq, bq, nullptr, pq, HQ*HD,  D);
    sgemm_nt<<<dim3((HKV*HD)/64, BSROWS/64), 256>>>(ph, wk, bk, nullptr, pk, HKV*HD, D);
    sgemm_nt<<<dim3((HKV*HD)/64, BSROWS/64), 256>>>(ph, wv, bv, nullptr, pv, HKV*HD, D);
    // 6. rope
    rope_kernel<<<BSROWS, 256>>>();
    // 7. attention
    attn_kernel<<<dim3(BSROWS, HQ/8), dim3(32, 8)>>>();
    // 8. o-proj + residual into x
    sgemm_nt<<<dim3(D/64, BSROWS/64), 256>>>(pctx, wo, nullptr, px, px, D, HQ*HD);
    // 9. rmsnorm2
    rmsnorm_kernel<<<BSROWS, 256>>>(px, ph, ln2w);
    // 10. MLP
    sgemm_nt<<<dim3(FF/64, BSROWS/64), 256>>>(ph, wgate, nullptr, nullptr, pg, FF, D);
    sgemm_nt<<<dim3(FF/64, BSROWS/64), 256>>>(ph, wup,   nullptr, nullptr, pu, FF, D);
    silu_mul_kernel<<<BSROWS, 256>>>();
    sgemm_nt<<<dim3(D/64, BSROWS/64), 256>>>(pg, wdown, nullptr, px, px, D, FF);
    // 11. output
    copy_kernel<<<(BSROWS*(size_t)D)/(256*4), 256>>>(hs, out);
    scatter_kernel<<<BSROWS, 256>>>(out);
}

// round 3
// speedup vs baseline: 5.2156x; 5.2156x over previous
#include <cuda_runtime.h>
#include <cuda_bf16.h>
#include <math.h>
#include <stdint.h>

// ---------------- problem constants ----------------
#define B   2
#define S   2048
#define D   2048
#define HQ  16
#define HKV 8
#define HD  128
#define FF  8192
#define KCAP 256
#define BSROWS (B*S)          // 4096
#define RMAX 512
#define EPSF 1e-6f
#define K3D (3*D)             // 6144
#define K3F (3*FF)            // 24576

// ---------------- device scratch ----------------
__device__ float d_rw[BSROWS];
__device__ float d_thresh[B];
__device__ int   d_selidx[BSROWS];
__device__ int   d_selcnt[B];
__device__ int   d_off[B+1];
__device__ int   d_rows[1];
__device__ int   d_row_b[RMAX];
__device__ int   d_row_p[RMAX];
__device__ float d_x   [(size_t)RMAX*D];
__device__ float d_h   [(size_t)RMAX*D];
__device__ float d_q   [(size_t)RMAX*HQ*HD];
__device__ float d_k   [(size_t)RMAX*HKV*HD];
__device__ float d_v   [(size_t)RMAX*HKV*HD];
__device__ float d_ctx [(size_t)RMAX*HQ*HD];
__device__ float d_gg  [(size_t)RMAX*FF];
__device__ float d_uu  [(size_t)RMAX*FF];
__device__ float d_part[(size_t)4*RMAX*D];

// converted (split-bf16, K-tripled) weights and activations
// offsets: wq 0 | wk | wv | wo | wgate | wup | wdown
#define OFF_WQ 0
#define OFF_WK (OFF_WQ + (size_t)2048*K3D)
#define OFF_WV (OFF_WK + (size_t)1024*K3D)
#define OFF_WO (OFF_WV + (size_t)1024*K3D)
#define OFF_WG (OFF_WO + (size_t)2048*K3D)
#define OFF_WU (OFF_WG + (size_t)8192*K3D)
#define OFF_WD (OFF_WU + (size_t)8192*K3D)
#define W3_TOTAL (OFF_WD + (size_t)2048*K3F)   // 188,743,680
__device__ __nv_bfloat16 d_w3[W3_TOTAL];
__device__ __nv_bfloat16 d_a3[(size_t)RMAX*K3F];

// ---------------- small helpers ----------------
__device__ __forceinline__ uint32_t smem_to_u32(const void* p) {
    uint32_t a;
    asm("{ .reg .u64 t; cvta.to.shared.u64 t, %1; cvt.u32.u64 %0, t; }" : "=r"(a) : "l"(p));
    return a;
}
__device__ __forceinline__ void cp_async16(uint32_t dst, const void* src, int sz) {
    asm volatile("cp.async.cg.shared.global [%0], [%1], 16, %2;"
                 :: "r"(dst), "l"(src), "r"(sz) : "memory");
}
__device__ __forceinline__ void cp_commit() { asm volatile("cp.async.commit_group;" ::: "memory"); }
__device__ __forceinline__ void cp_wait1()  { asm volatile("cp.async.wait_group 1;" ::: "memory"); }
__device__ __forceinline__ void ldsm4(uint32_t& r0, uint32_t& r1, uint32_t& r2, uint32_t& r3, uint32_t a) {
    asm volatile("ldmatrix.sync.aligned.m8n8.x4.shared.b16 {%0,%1,%2,%3}, [%4];"
                 : "=r"(r0), "=r"(r1), "=r"(r2), "=r"(r3) : "r"(a));
}
__device__ __forceinline__ void mma_bf16(float* c, const uint32_t* a, uint32_t b0, uint32_t b1) {
    asm volatile("mma.sync.aligned.m16n8k16.row.col.f32.bf16.bf16.f32 "
                 "{%0,%1,%2,%3}, {%4,%5,%6,%7}, {%8,%9}, {%0,%1,%2,%3};"
                 : "+f"(c[0]), "+f"(c[1]), "+f"(c[2]), "+f"(c[3])
                 : "r"(a[0]), "r"(a[1]), "r"(a[2]), "r"(a[3]), "r"(b0), "r"(b1));
}
__device__ __forceinline__ uint32_t pack_bf2(float a, float b) {
    __nv_bfloat162 t = __floats2bfloat162_rn(a, b);
    return *(uint32_t*)&t;
}

// ---------------- weight conversion: W[N][K] f32 -> W3[N][3K] bf16 [hi|hi|lo] ----------------
__global__ void convert_w_kernel(const float* __restrict__ src, __nv_bfloat16* __restrict__ dst,
                                 int N, int K) {
    int idx = blockIdx.x * 256 + threadIdx.x;
    int kq = K >> 2;
    if (idx >= N * kq) return;
    int n = idx / kq, c4 = (idx - n * kq) << 2;
    float4 v = *(const float4*)(src + (size_t)n * K + c4);
    float hx = __bfloat162float(__float2bfloat16(v.x));
    float hy = __bfloat162float(__float2bfloat16(v.y));
    float hz = __bfloat162float(__float2bfloat16(v.z));
    float hw = __bfloat162float(__float2bfloat16(v.w));
    uint2 hi = make_uint2(pack_bf2(hx, hy), pack_bf2(hz, hw));
    uint2 lo = make_uint2(pack_bf2(v.x - hx, v.y - hy), pack_bf2(v.z - hz, v.w - hw));
    size_t b = (size_t)n * 3 * K + c4;
    *(uint2*)(dst + b)         = hi;
    *(uint2*)(dst + b + K)     = hi;
    *(uint2*)(dst + b + 2*K)   = lo;
}

// ---------------- activation conversion: A[g][K] f32 -> A3[g][3K] bf16 [hi|lo|hi] ----------------
__global__ void convert_a_kernel(const float* __restrict__ src, __nv_bfloat16* __restrict__ dst, int K) {
    int g = blockIdx.x;
    if (g >= d_rows[0]) return;
    const float* row = src + (size_t)g * K;
    __nv_bfloat16* drow = dst + (size_t)g * 3 * K;
    for (int c4 = threadIdx.x * 4; c4 < K; c4 += 256 * 4) {
        float4 v = *(const float4*)(row + c4);
        float hx = __bfloat162float(__float2bfloat16(v.x));
        float hy = __bfloat162float(__float2bfloat16(v.y));
        float hz = __bfloat162float(__float2bfloat16(v.z));
        float hw = __bfloat162float(__float2bfloat16(v.w));
        uint2 hi = make_uint2(pack_bf2(hx, hy), pack_bf2(hz, hw));
        uint2 lo = make_uint2(pack_bf2(v.x - hx, v.y - hy), pack_bf2(v.z - hz, v.w - hw));
        *(uint2*)(drow + c4)         = hi;
        *(uint2*)(drow + c4 + K)     = lo;
        *(uint2*)(drow + c4 + 2*K)   = hi;
    }
}

// ---------------- tensor-core GEMM via mma.sync (bf16, fp32 accum) ----------------
// C[M,N] = A3[M,K3] @ W3[N,K3]^T (+bias). Up to 3 output segments sharing A.
// CTA tile 128x128, BK=32, 3-stage cp.async pipeline, 8 warps x (64x32) warp tiles.
struct Seg { const __nv_bfloat16* W3; const float* bias; float* C; int N; int ntiles; };
struct GArgs { const __nv_bfloat16* A3; int K3; int kSplit; int nseg; Seg s[3]; };

#define STAGES 3
#define STAGE_BYTES 16384   // A 8KB + W 8KB

__global__ void __launch_bounds__(256) mma_gemm(GArgs ga) {
    extern __shared__ char smem[];
    uint32_t sb = smem_to_u32(smem);
    int tid = threadIdx.x;
    int rows = d_rows[0]; if (rows > RMAX) rows = RMAX;
    int m0 = blockIdx.y * 128;

    Seg sg = ga.s[0];
    int nt = blockIdx.x;
    if (ga.nseg > 1 && nt >= ga.s[0].ntiles) {
        nt -= ga.s[0].ntiles; sg = ga.s[1];
        if (ga.nseg > 2 && nt >= ga.s[1].ntiles) { nt -= ga.s[1].ntiles; sg = ga.s[2]; }
    }
    int n0g = nt * 128;
    int kLen = ga.K3 / ga.kSplit;
    int kOff = blockIdx.z * kLen;
    int iters = kLen / 32;

    const __nv_bfloat16* Abase = ga.A3;
    const __nv_bfloat16* Wbase = sg.W3 + (size_t)n0g * ga.K3;

    // loader mapping: thread does 2 A-chunks + 2 W-chunks of 16B per stage
    int lrow[2], lc[2]; uint32_t lsw[2];
    #pragma unroll
    for (int q = 0; q < 2; q++) {
        int j = tid + q * 256;
        lrow[q] = j >> 2; lc[q] = j & 3;
        lsw[q] = lrow[q] * 64 + ((lc[q] ^ ((lrow[q] >> 1) & 3)) << 4);
    }

    #define LOAD_STAGE(stage, kElem) do { \
        uint32_t sA = sb + (stage) * STAGE_BYTES; \
        uint32_t sW = sA + 8192; \
        _Pragma("unroll") \
        for (int q = 0; q < 2; q++) { \
            int gm = m0 + lrow[q]; \
            cp_async16(sA + lsw[q], Abase + (size_t)gm * ga.K3 + (kElem) + lc[q]*8, gm < rows ? 16 : 0); \
            cp_async16(sW + lsw[q], Wbase + (size_t)lrow[q] * ga.K3 + (kElem) + lc[q]*8, 16); \
        } \
    } while (0)

    // prologue
    LOAD_STAGE(0, kOff); cp_commit();
    LOAD_STAGE(1, kOff + 32); cp_commit();

    int lane = tid & 31, wid = tid >> 5;
    int wm = wid >> 2, wn = wid & 3;
    float acc[4][4][4];
    #pragma unroll
    for (int a = 0; a < 4; a++)
        #pragma unroll
        for (int b = 0; b < 4; b++)
            #pragma unroll
            for (int c = 0; c < 4; c++) acc[a][b][c] = 0.f;

    // precompute ldmatrix smem offsets (within stage)
    uint32_t aoff[4], boff[2];
    #pragma unroll
    for (int mi = 0; mi < 4; mi++) {
        int row = wm * 64 + mi * 16 + (lane & 15);
        int ch = lane >> 4;                       // +2*s2 applied at use
        aoff[mi] = row * 64 + (((ch) ^ ((row >> 1) & 3)) << 4);
        // store row and base ch separately via recompute at use; keep row-part:
        aoff[mi] = row * 64; // recompute chunk at use
    }
    int arow_[4], ach_;
    #pragma unroll
    for (int mi = 0; mi < 4; mi++) arow_[mi] = wm * 64 + mi * 16 + (lane & 15);
    ach_ = lane >> 4;
    int brow_[2], bch_;
    #pragma unroll
    for (int p = 0; p < 2; p++) brow_[p] = wn * 32 + p * 16 + (lane & 7) + ((lane >> 4) << 3);
    bch_ = (lane >> 3) & 1;

    for (int i = 0; i < iters; i++) {
        cp_wait1();
        __syncthreads();
        int nf = i + STAGES - 1;
        if (nf < iters) LOAD_STAGE(nf % STAGES, kOff + nf * 32);
        cp_commit();

        uint32_t sA = sb + (i % STAGES) * STAGE_BYTES;
        uint32_t sW = sA + 8192;
        #pragma unroll
        for (int s2 = 0; s2 < 2; s2++) {
            uint32_t af[4][4];
            #pragma unroll
            for (int mi = 0; mi < 4; mi++) {
                int row = arow_[mi];
                int ch = 2 * s2 + ach_;
                uint32_t ad = sA + row * 64 + ((ch ^ ((row >> 1) & 3)) << 4);
                ldsm4(af[mi][0], af[mi][1], af[mi][2], af[mi][3], ad);
            }
            uint32_t b0[4], b1[4];
            #pragma unroll
            for (int p = 0; p < 2; p++) {
                int row = brow_[p];
                int ch = 2 * s2 + bch_;
                uint32_t bd = sW + row * 64 + ((ch ^ ((row >> 1) & 3)) << 4);
                uint32_t r0, r1, r2, r3;
                ldsm4(r0, r1, r2, r3, bd);
                b0[2*p] = r0; b1[2*p] = r1; b0[2*p+1] = r2; b1[2*p+1] = r3;
            }
            #pragma unroll
            for (int mi = 0; mi < 4; mi++)
                #pragma unroll
                for (int ni = 0; ni < 4; ni++)
                    mma_bf16(acc[mi][ni], af[mi], b0[ni], b1[ni]);
        }
        __syncthreads();
    }

    // epilogue
    float* Cp = sg.C + (ga.kSplit > 1 ? (size_t)blockIdx.z * RMAX * sg.N : 0);
    int rr = lane >> 2;
    int cc = (lane & 3) * 2;
    #pragma unroll
    for (int mi = 0; mi < 4; mi++) {
        int m1 = m0 + wm * 64 + mi * 16 + rr;
        #pragma unroll
        for (int ni = 0; ni < 4; ni++) {
            int n1 = n0g + wn * 32 + ni * 8 + cc;
            float bx = 0.f, by = 0.f;
            if (sg.bias) { bx = sg.bias[n1]; by = sg.bias[n1 + 1]; }
            if (m1 < rows) {
                float2 v0 = make_float2(acc[mi][ni][0] + bx, acc[mi][ni][1] + by);
                *(float2*)(Cp + (size_t)m1 * sg.N + n1) = v0;
            }
            if (m1 + 8 < rows) {
                float2 v1 = make_float2(acc[mi][ni][2] + bx, acc[mi][ni][3] + by);
                *(float2*)(Cp + (size_t)(m1 + 8) * sg.N + n1) = v1;
            }
        }
    }
    #undef LOAD_STAGE
}

// ---------------- split-K reduce into d_x (residual already there) ----------------
__global__ void reduce_kernel(int nparts) {
    int g = blockIdx.x;
    if (g >= d_rows[0]) return;
    for (int c = threadIdx.x; c < D; c += 256) {
        size_t o = (size_t)g * D + c;
        float s = d_x[o];
        for (int p = 0; p < nparts; p++) s += d_part[(size_t)p * RMAX * D + o];
        d_x[o] = s;
    }
}

// ---------------- router / topk / select / map ----------------
__global__ void router_kernel(const float* __restrict__ hs, const float* __restrict__ rwv) {
    int row  = blockIdx.x * 8 + (threadIdx.x >> 5);
    int lane = threadIdx.x & 31;
    if (row >= BSROWS) return;
    const float* x = hs + (size_t)row * D;
    float s = 0.f;
    for (int i = lane; i < D; i += 32) s += x[i] * rwv[i];
    #pragma unroll
    for (int o = 16; o; o >>= 1) s += __shfl_xor_sync(0xffffffffu, s, o);
    if (lane == 0) d_rw[row] = s;
}

__global__ void topk_kernel() {
    __shared__ float s[S];
    int b = blockIdx.x;
    int t = threadIdx.x;
    s[t] = d_rw[b*S + t]; s[t + 1024] = d_rw[b*S + t + 1024];
    for (int k = 2; k <= S; k <<= 1)
        for (int j = k >> 1; j > 0; j >>= 1) {
            __syncthreads();
            for (int i = t; i < S; i += 1024) {
                int ixj = i ^ j;
                if (ixj > i) {
                    bool up = ((i & k) == 0);
                    float a = s[i], c = s[ixj];
                    if ((a > c) == up) { s[i] = c; s[ixj] = a; }
                }
            }
        }
    __syncthreads();
    if (t == 0) d_thresh[b] = s[S - KCAP];
}

__global__ void select_kernel() {
    int b = blockIdx.x, lane = threadIdx.x;
    if (lane >= 32) return;
    float th = d_thresh[b];
    int total = 0;
    for (int c = 0; c < S/32; c++) {
        int idx = c*32 + lane;
        bool f = d_rw[b*S + idx] >= th;
        unsigned m = __ballot_sync(0xffffffffu, f);
        int pre = __popc(m & ((1u << lane) - 1u));
        if (f) d_selidx[b*S + total + pre] = idx;
        total += __popc(m);
    }
    if (lane == 0) d_selcnt[b] = total;
}

__global__ void map_kernel() {
    int t = threadIdx.x;
    int c0 = d_selcnt[0], c1 = d_selcnt[1];
    int rows = c0 + c1; if (rows > RMAX) rows = RMAX;
    if (t == 0) { d_off[0]=0; d_off[1]=c0; d_off[2]=c0+c1; d_rows[0]=rows; }
    for (int i = t; i < c0; i += blockDim.x) if (i < RMAX)      { d_row_b[i]      = 0; d_row_p[i]      = d_selidx[i]; }
    for (int i = t; i < c1; i += blockDim.x) if (c0 + i < RMAX) { d_row_b[c0 + i] = 1; d_row_p[c0 + i] = d_selidx[S + i]; }
}

// ---------------- gather + rmsnorm fused ----------------
__global__ void gather_rms_kernel(const float* __restrict__ hs, const float* __restrict__ w) {
    int g = blockIdx.x;
    if (g >= d_rows[0]) return;
    int b = d_row_b[g], p = d_row_p[g];
    const float4* src = (const float4*)(hs + ((size_t)b*S + p) * D);
    float4* dx = (float4*)(d_x + (size_t)g * D);
    float ss = 0.f;
    for (int i = threadIdx.x; i < D/4; i += 256) {
        float4 v = src[i]; dx[i] = v;
        ss += v.x*v.x + v.y*v.y + v.z*v.z + v.w*v.w;
    }
    __shared__ float red[8];
    int lane = threadIdx.x & 31, wid = threadIdx.x >> 5;
    #pragma unroll
    for (int o = 16; o; o >>= 1) ss += __shfl_xor_sync(0xffffffffu, ss, o);
    if (lane == 0) red[wid] = ss;
    __syncthreads();
    if (threadIdx.x == 0) { float v=0.f; for (int i=0;i<8;i++) v+=red[i]; red[0]=v; }
    __syncthreads();
    float inv = rsqrtf(red[0] / (float)D + EPSF);
    float4* dh = (float4*)(d_h + (size_t)g * D);
    const float4* wv4 = (const float4*)w;
    for (int i = threadIdx.x; i < D/4; i += 256) {
        float4 v = dx[i], ww = wv4[i];
        dh[i] = make_float4(v.x*inv*ww.x, v.y*inv*ww.y, v.z*inv*ww.z, v.w*inv*ww.w);
    }
}

__global__ void rmsnorm_kernel(const float* __restrict__ in, float* __restrict__ out,
                               const float* __restrict__ w) {
    int g = blockIdx.x;
    if (g >= d_rows[0]) return;
    const float* row = in + (size_t)g * D;
    float ss = 0.f;
    for (int i = threadIdx.x; i < D; i += 256) { float v = row[i]; ss += v*v; }
    __shared__ float red[8];
    int lane = threadIdx.x & 31, wid = threadIdx.x >> 5;
    #pragma unroll
    for (int o = 16; o; o >>= 1) ss += __shfl_xor_sync(0xffffffffu, ss, o);
    if (lane == 0) red[wid] = ss;
    __syncthreads();
    if (threadIdx.x == 0) { float v=0.f; for (int i=0;i<8;i++) v+=red[i]; red[0]=v; }
    __syncthreads();
    float inv = rsqrtf(red[0] / (float)D + EPSF);
    for (int i = threadIdx.x; i < D; i += 256) out[(size_t)g*D + i] = row[i] * inv * w[i];
}

// ---------------- RoPE ----------------
__global__ void rope_kernel() {
    int g = blockIdx.x;
    if (g >= d_rows[0]) return;
    float fp = (float)d_row_p[g];
    const float L2_10000 = 13.287712379549449f;
    for (int idx = threadIdx.x; idx < (HQ + HKV) * 64; idx += 256) {
        int head = idx >> 6;
        int i = idx & 63;
        float inv = exp2f(-(float)i * (L2_10000 / 64.0f));
        float fr = fp * inv;
        float c = cosf(fr), s = sinf(fr);
        float* ptr;
        if (head < HQ) ptr = d_q + (size_t)g*(HQ*HD) + head*HD;
        else           ptr = d_k + (size_t)g*(HKV*HD) + (head-HQ)*HD;
        float x1 = ptr[i], x2 = ptr[i+64];
        ptr[i]    = x1*c - x2*s;
        ptr[i+64] = x2*c + x1*s;
    }
}

// ---------------- attention ----------------
__global__ void attn_kernel() {
    int g = blockIdx.x;
    if (g >= d_rows[0]) return;
    int h = threadIdx.y + blockIdx.y * 8;
    int b = d_row_b[g];
    int off = d_off[b];
    int r = g - off;
    int p = d_row_p[g];
    int lane = threadIdx.x;
    int kvh = h >> 1;

    float4 qv = *(const float4*)(d_q + (size_t)g*(HQ*HD) + h*HD + lane*4);
    const float scale = 0.08838834764831843f;

    float m = -INFINITY, l = 0.f;
    float4 acc = make_float4(0.f, 0.f, 0.f, 0.f);

    for (int j = 0; j <= r; j++) {
        const float* kp = d_k + (size_t)(off + j)*(HKV*HD) + kvh*HD;
        float4 kv = *(const float4*)(kp + lane*4);
        float sdot = qv.x*kv.x + qv.y*kv.y + qv.z*kv.z + qv.w*kv.w;
        #pragma unroll
        for (int o = 16; o; o >>= 1) sdot += __shfl_xor_sync(0xffffffffu, sdot, o);
        float sc = sdot * scale;
        float mn = fmaxf(m, sc);
        float eo = expf(m - mn);
        float ec = expf(sc - mn);
        const float* vp = d_v + (size_t)(off + j)*(HKV*HD) + kvh*HD;
        float4 vv = *(const float4*)(vp + lane*4);
        l = l*eo + ec;
        acc.x = acc.x*eo + ec*vv.x;
        acc.y = acc.y*eo + ec*vv.y;
        acc.z = acc.z*eo + ec*vv.z;
        acc.w = acc.w*eo + ec*vv.w;
        m = mn;
    }
    int zc = p - r;
    if (zc > 0) {
        float mn = fmaxf(m, 0.f);
        float eo = expf(m - mn);
        l = l*eo + (float)zc * expf(-mn);
        acc.x *= eo; acc.y *= eo; acc.z *= eo; acc.w *= eo;
    }
    float invl = 1.f / l;
    *(float4*)(d_ctx + (size_t)g*(HQ*HD) + h*HD + lane*4) =
        make_float4(acc.x*invl, acc.y*invl, acc.z*invl, acc.w*invl);
}

// ---------------- silu(g)*u ----------------
__global__ void silu_mul_kernel() {
    int g = blockIdx.x;
    if (g >= d_rows[0]) return;
    size_t base = (size_t)g * FF;
    for (int i = threadIdx.x; i < FF; i += 256) {
        float x = d_gg[base + i];
        float u = d_uu[base + i];
        d_gg[base + i] = (x / (1.f + expf(-x))) * u;
    }
}

// ---------------- output ----------------
__global__ void copy_kernel(const float* __restrict__ hs, float* __restrict__ out) {
    size_t i = ((size_t)blockIdx.x * 256 + threadIdx.x);
    ((float4*)out)[i] = ((const float4*)hs)[i];
}

__global__ void scatter_kernel(float* __restrict__ out) {
    int g = blockIdx.x;
    if (g >= d_rows[0]) return;
    int b = d_row_b[g], p = d_row_p[g];
    float sc = d_rw[b*S + p];
    float* dst = out + ((size_t)b*S + p) * D;
    const float* src = d_x + (size_t)g * D;
    for (int i = threadIdx.x; i < D; i += 256) dst[i] = src[i] * sc;
}

// ---------------- launch ----------------
extern "C" void kernel_launch(void* const* d_in, const int* in_sizes, int n_in,
                              void* d_out, int out_size) {
    const float* hs    = (const float*)d_in[0];
    const float* rwv   = (const float*)d_in[1];
    const float* wq    = (const float*)d_in[2];
    const float* bq    = (const float*)d_in[3];
    const float* wk    = (const float*)d_in[4];
    const float* bk    = (const float*)d_in[5];
    const float* wv    = (const float*)d_in[6];
    const float* bv    = (const float*)d_in[7];
    const float* wo    = (const float*)d_in[8];
    const float* wgate = (const float*)d_in[9];
    const float* wup   = (const float*)d_in[10];
    const float* wdown = (const float*)d_in[11];
    const float* ln1w  = (const float*)d_in[12];
    const float* ln2w  = (const float*)d_in[13];
    float* out = (float*)d_out;

    float *px, *ph, *pq, *pk, *pv, *pctx, *pg, *pu;
    __nv_bfloat16 *pw3, *pa3;
    cudaGetSymbolAddress((void**)&px,    d_x);
    cudaGetSymbolAddress((void**)&ph,    d_h);
    cudaGetSymbolAddress((void**)&pq,    d_q);
    cudaGetSymbolAddress((void**)&pk,    d_k);
    cudaGetSymbolAddress((void**)&pv,    d_v);
    cudaGetSymbolAddress((void**)&pctx,  d_ctx);
    cudaGetSymbolAddress((void**)&pg,    d_gg);
    cudaGetSymbolAddress((void**)&pu,    d_uu);
    cudaGetSymbolAddress((void**)&pw3,   d_w3);
    cudaGetSymbolAddress((void**)&pa3,   d_a3);
    float* ppart;
    cudaGetSymbolAddress((void**)&ppart, d_part);

    static int attr_done = 0;
    if (!attr_done) {
        cudaFuncSetAttribute(mma_gemm, cudaFuncAttributeMaxDynamicSharedMemorySize, STAGES*STAGE_BYTES);
        attr_done = 1;
    }

    // weight conversions (every call; deterministic)
    convert_w_kernel<<<(2048*(D/4)+255)/256, 256>>>(wq,    pw3 + OFF_WQ, 2048, D);
    convert_w_kernel<<<(1024*(D/4)+255)/256, 256>>>(wk,    pw3 + OFF_WK, 1024, D);
    convert_w_kernel<<<(1024*(D/4)+255)/256, 256>>>(wv,    pw3 + OFF_WV, 1024, D);
    convert_w_kernel<<<(2048*(D/4)+255)/256, 256>>>(wo,    pw3 + OFF_WO, 2048, D);
    convert_w_kernel<<<(8192*(D/4)+255)/256, 256>>>(wgate, pw3 + OFF_WG, 8192, D);
    convert_w_kernel<<<(8192*(D/4)+255)/256, 256>>>(wup,   pw3 + OFF_WU, 8192, D);
    convert_w_kernel<<<(2048*(FF/4)+255)/256, 256>>>(wdown, pw3 + OFF_WD, 2048, FF);

    router_kernel<<<BSROWS/8, 256>>>(hs, rwv);
    topk_kernel<<<B, 1024>>>();
    select_kernel<<<B, 32>>>();
    map_kernel<<<1, 1024>>>();
    gather_rms_kernel<<<RMAX, 256>>>(hs, ln1w);
    convert_a_kernel<<<RMAX, 256>>>(ph, pa3, D);

    // QKV (segments q/k/v), K3=6144, no split
    {
        GArgs ga = {};
        ga.A3 = pa3; ga.K3 = K3D; ga.kSplit = 1; ga.nseg = 3;
        ga.s[0] = { pw3 + OFF_WQ, bq, pq, HQ*HD,  16 };
        ga.s[1] = { pw3 + OFF_WK, bk, pk, HKV*HD, 8  };
        ga.s[2] = { pw3 + OFF_WV, bv, pv, HKV*HD, 8  };
        mma_gemm<<<dim3(32, 4, 1), 256, STAGES*STAGE_BYTES>>>(ga);
    }
    rope_kernel<<<RMAX, 256>>>();
    attn_kernel<<<dim3(RMAX, HQ/8), dim3(32, 8)>>>();
    convert_a_kernel<<<RMAX, 256>>>(pctx, pa3, D);
    // O projection, split-K 2 -> partials, reduce adds residual-held d_x
    {
        GArgs ga = {};
        ga.A3 = pa3; ga.K3 = K3D; ga.kSplit = 2; ga.nseg = 1;
        ga.s[0] = { pw3 + OFF_WO, nullptr, ppart, D, 16 };
        mma_gemm<<<dim3(16, 4, 2), 256, STAGES*STAGE_BYTES>>>(ga);
    }
    reduce_kernel<<<RMAX, 256>>>(2);
    rmsnorm_kernel<<<RMAX, 256>>>(px, ph, ln2w);
    convert_a_kernel<<<RMAX, 256>>>(ph, pa3, D);
    // gate + up merged
    {
        GArgs ga = {};
        ga.A3 = pa3; ga.K3 = K3D; ga.kSplit = 1; ga.nseg = 2;
        ga.s[0] = { pw3 + OFF_WG, nullptr, pg, FF, 64 };
        ga.s[1] = { pw3 + OFF_WU, nullptr, pu, FF, 64 };
        mma_gemm<<<dim3(128, 4, 1), 256, STAGES*STAGE_BYTES>>>(ga);
    }
    silu_mul_kernel<<<RMAX, 256>>>();
    convert_a_kernel<<<RMAX, 256>>>(pg, pa3, FF);
    // down, split-K 4
    {
        GArgs ga = {};
        ga.A3 = pa3; ga.K3 = K3F; ga.kSplit = 4; ga.nseg = 1;
        ga.s[0] = { pw3 + OFF_WD, nullptr, ppart, D, 16 };
        mma_gemm<<<dim3(16, 4, 4), 256, STAGES*STAGE_BYTES>>>(ga);
    }
    reduce_kernel<<<RMAX, 256>>>(4);

    copy_kernel<<<(BSROWS*(size_t)D)/(256*4), 256>>>(hs, out);
    scatter_kernel<<<RMAX, 256>>>(out);
}